// round 5
// baseline (speedup 1.0000x reference)
#include <cuda_runtime.h>
#include <cstdint>

// YOLOv7 P3 head decode: [B, A*(5+NC), H, W] -> [B, A*H*W, 5+NC]
// B=16, A=3, NC=80, H=W=80, stride=8.
//
// Round-4: TILE=64 per block. 6 independent LDG.128 staged per thread
// (doubles per-warp MLP vs round 3), half the blocks/barriers per byte.
// Load phase: channel-major coalesced float4 reads, transform in regs,
// conflict-free scatter STS into position-major smem. Store phase:
// batched LDS.128 -> contiguous streaming STG.128.

constexpr int A_ = 3;
constexpr int C_ = 85;        // 5 + 80
constexpr int W_ = 80;
constexpr int HW = 80 * 80;   // 6400
constexpr int TILE = 64;      // positions per block
constexpr int TILES_PER_SLICE = HW / TILE;   // 100
constexpr int NSLICES = 16 * A_;             // 48
constexpr int UNITS = C_ * (TILE / 4);       // 1360 float4 units
constexpr float STRIDE = 8.0f;               // 640 / 80

__device__ __forceinline__ float sigmoidf_(float v) {
    return 1.0f / (1.0f + __expf(-v));
}

__device__ __forceinline__ float expclipf_(float v) {
    return __expf(fminf(fmaxf(v, -16.0f), 16.0f));
}

__global__ __launch_bounds__(256) void yolo_head_kernel(
    const float* __restrict__ in,
    const float* __restrict__ anchors,
    float* __restrict__ out)
{
    __shared__ float sm[TILE * C_];          // position-major, stride 85 (odd)

    const int tid    = threadIdx.x;
    const int tileId = blockIdx.x;                       // 0 .. 4799
    const int slice  = tileId / TILES_PER_SLICE;         // b*A + a
    const int p0     = (tileId % TILES_PER_SLICE) * TILE;
    const int a      = slice % A_;

    const float* inBase = in + (size_t)slice * C_ * HW + p0;

    // unit idx = tid + 256*k  ->  c = (tid>>4) + 16k,  p = (tid&15)*4
    const int c0 = tid >> 4;                 // 0..15
    const int p  = (tid & 15) << 2;          // 0,4,...,60
    const bool act5 = tid < (UNITS - 5 * 256);   // tid < 80

    // ---- Stage ALL global loads: 6 independent LDG.128 in flight.
    float4 v0 = __ldcs(reinterpret_cast<const float4*>(inBase + (size_t)(c0      ) * HW + p));
    float4 v1 = __ldcs(reinterpret_cast<const float4*>(inBase + (size_t)(c0 + 16 ) * HW + p));
    float4 v2 = __ldcs(reinterpret_cast<const float4*>(inBase + (size_t)(c0 + 32 ) * HW + p));
    float4 v3 = __ldcs(reinterpret_cast<const float4*>(inBase + (size_t)(c0 + 48 ) * HW + p));
    float4 v4 = __ldcs(reinterpret_cast<const float4*>(inBase + (size_t)(c0 + 64 ) * HW + p));
    float4 v5;
    if (act5)
        v5 = __ldcs(reinterpret_cast<const float4*>(inBase + (size_t)(c0 + 80) * HW + p));

    // ---- Transform + scatter. Special channels (0..3) only in k=0 (c0<4).
    {
        float r[4];
        float vv[4] = {v0.x, v0.y, v0.z, v0.w};
        if (c0 >= 4) {
            #pragma unroll
            for (int i = 0; i < 4; i++) r[i] = sigmoidf_(vv[i]);
        } else if (c0 == 0) {
            #pragma unroll
            for (int i = 0; i < 4; i++) {
                const int pos = p0 + p + i;
                const int gx  = pos - (pos / W_) * W_;
                r[i] = (sigmoidf_(vv[i]) + (float)gx) * STRIDE;
            }
        } else if (c0 == 1) {
            #pragma unroll
            for (int i = 0; i < 4; i++) {
                const int gy = (p0 + p + i) / W_;
                r[i] = (sigmoidf_(vv[i]) + (float)gy) * STRIDE;
            }
        } else {
            const float an = anchors[a * 2 + (c0 - 2)];
            #pragma unroll
            for (int i = 0; i < 4; i++) r[i] = expclipf_(vv[i]) * an;
        }
        #pragma unroll
        for (int i = 0; i < 4; i++) sm[(p + i) * C_ + c0] = r[i];
    }
    {
        float vv[4] = {v1.x, v1.y, v1.z, v1.w};
        #pragma unroll
        for (int i = 0; i < 4; i++) sm[(p + i) * C_ + (c0 + 16)] = sigmoidf_(vv[i]);
    }
    {
        float vv[4] = {v2.x, v2.y, v2.z, v2.w};
        #pragma unroll
        for (int i = 0; i < 4; i++) sm[(p + i) * C_ + (c0 + 32)] = sigmoidf_(vv[i]);
    }
    {
        float vv[4] = {v3.x, v3.y, v3.z, v3.w};
        #pragma unroll
        for (int i = 0; i < 4; i++) sm[(p + i) * C_ + (c0 + 48)] = sigmoidf_(vv[i]);
    }
    {
        float vv[4] = {v4.x, v4.y, v4.z, v4.w};
        #pragma unroll
        for (int i = 0; i < 4; i++) sm[(p + i) * C_ + (c0 + 64)] = sigmoidf_(vv[i]);
    }
    if (act5) {
        float vv[4] = {v5.x, v5.y, v5.z, v5.w};
        #pragma unroll
        for (int i = 0; i < 4; i++) sm[(p + i) * C_ + (c0 + 80)] = sigmoidf_(vv[i]);
    }

    __syncthreads();

    // ---- Copy-out: batch LDS.128, then contiguous streaming STG.128.
    // Tile output = 5440 consecutive floats; p0*85 multiple of 4 -> aligned.
    const float4* sm4 = reinterpret_cast<const float4*>(sm);
    float4* outBase4  = reinterpret_cast<float4*>(
        out + (size_t)slice * HW * C_ + (size_t)p0 * C_);

    float4 o0 = sm4[tid];
    float4 o1 = sm4[tid + 256];
    float4 o2 = sm4[tid + 512];
    float4 o3 = sm4[tid + 768];
    float4 o4 = sm4[tid + 1024];
    float4 o5;
    if (act5) o5 = sm4[tid + 1280];

    __stcs(&outBase4[tid],        o0);
    __stcs(&outBase4[tid + 256],  o1);
    __stcs(&outBase4[tid + 512],  o2);
    __stcs(&outBase4[tid + 768],  o3);
    __stcs(&outBase4[tid + 1024], o4);
    if (act5) __stcs(&outBase4[tid + 1280], o5);
}

extern "C" void kernel_launch(void* const* d_in, const int* in_sizes, int n_in,
                              void* d_out, int out_size) {
    const float* in      = (const float*)d_in[0];
    const float* anchors = (const float*)d_in[1];
    float* out           = (float*)d_out;

    const int nBlocks = NSLICES * TILES_PER_SLICE;   // 4800
    yolo_head_kernel<<<nBlocks, 256>>>(in, anchors, out);
}